// round 11
// baseline (speedup 1.0000x reference)
#include <cuda_runtime.h>
#include <math_constants.h>

// ---------------------------------------------------------------------------
// Exact 3-NN interpolation via grid ring-search — fused kernel v5.
// Skeleton = R7 (proven 27.1us): persistent grid, TWO grid barriers, search +
// weights + gather fused in one pass, no scratch round-trip.
// Change vs R7: HALF-WARP-per-task. Lanes 0-15 own task 2*pair, lanes 16-31
// own task 2*pair+1 (scale-major ids -> same scale, lockstep halves).
//   - each lane scans <=2 of the 27 rr=1 cells
//   - 4-step shfl_xor butterfly merge within the half (disjoint keys -> ins3)
//   - after merge all 16 lanes hold the identical top-3 -> stop test is LOCAL
//     (no warp reduction on the hot path at all)
//   - rare rr>=2 fallback in-place in the half-warp (dedup ins3d merges)
//   - half-warp float4 gather
//
// Exactness: candidate (d2,row) pairs form a total lexicographic order (rows
// unique per scale; duplicate voxels give bitwise-equal d2, per-cell slots
// sorted by row), so strict lex insertion + merge = stable jax.lax.top_k.
// Butterfly merge exact: top3(A u B) subset of top3(A) u top3(B); rr=1 lists
// are key-disjoint across lanes (cells partitioned); fallback merges use
// row-dedup ins3d (R4-proven). Stop rule: after Chebyshev radius rr, any
// unexamined center is >= (rr+0.5)*vs away (point inside its own cell); >=3
// candidates strictly inside the conservatively-shrunk bound => exact.
// Distance math: explicit __fmul_rn/__fadd_rn in reference op order.
// ---------------------------------------------------------------------------

#define NPTS   8192
#define OUTC   480
#define INF_I  0x7fffffff

#define MB0 0
#define MB1 32768
#define MB2 (32768 + 4096)
#define MB3 (32768 + 4096 + 512)
#define MCELLS (32768 + 4096 + 512 + 64)

#define GRID     740                   // 5 blocks/SM * 148 SMs, all resident
#define TPB      256
#define NTHREADS (GRID * TPB)          // 189440
#define NWARPS   (NTHREADS / 32)       // 5920
#define NTASKS   (NPTS * 4)            // 32768
#define NPAIRS   (NTASKS / 2)          // 16384
#define NROWS    20576                 // 16000 + 4000 + 512 + 64

__device__ int4     g_map[MCELLS];
__device__ unsigned g_cnt[2];
__device__ unsigned g_phase[2];        // monotone senses; never reset

__device__ __forceinline__ void grid_bar(int b)
{
    __syncthreads();
    if (threadIdx.x == 0) {
        volatile unsigned* ph = &g_phase[b];
        unsigned p0 = *ph;
        __threadfence();
        unsigned prev = atomicAdd(&g_cnt[b], 1u);
        if (prev == GRID - 1) {
            g_cnt[b] = 0;
            __threadfence();
            *ph = p0 + 1u;
        } else {
            while (*ph == p0) { }
        }
        __threadfence();
    }
    __syncthreads();
}

__device__ __forceinline__ bool diless(float da, int ia, float db, int ib) {
    return (da < db) || (da == db && ia < ib);
}

__device__ __forceinline__ void ins3(float d, int i,
                                     float& d0, int& i0,
                                     float& d1, int& i1,
                                     float& d2, int& i2) {
    if (diless(d, i, d2, i2)) {
        d2 = d; i2 = i;
        if (diless(d2, i2, d1, i1)) { float td = d1; d1 = d2; d2 = td; int ti = i1; i1 = i2; i2 = ti; }
        if (diless(d1, i1, d0, i0)) { float td = d0; d0 = d1; d1 = td; int ti = i0; i0 = i1; i1 = ti; }
    }
}

// dedup-guarded insert (rows are unique keys) for post-convergence merges
__device__ __forceinline__ void ins3d(float d, int i,
                                      float& d0, int& i0,
                                      float& d1, int& i1,
                                      float& d2, int& i2) {
    if (i != i0 && i != i1 && i != i2)
        ins3(d, i, d0, i0, d1, i1, d2, i2);
}

__device__ __forceinline__ void visit_cell(
    int jx, int jy, int jz, int g, int base,
    float vs, float OFF, float HALF,
    float px, float py, float pz,
    float& d0, int& r0, float& d1, int& r1, float& d2, int& r2)
{
    if ((unsigned)jx >= (unsigned)g || (unsigned)jy >= (unsigned)g ||
        (unsigned)jz >= (unsigned)g) return;

    int4 s = g_map[base + (jx * g + jy) * g + jz];
    if (s.x == INF_I) return;

    float qx = __fadd_rn(__fadd_rn(__fmul_rn((float)jx, vs), OFF), HALF);
    float qy = __fadd_rn(__fadd_rn(__fmul_rn((float)jy, vs), OFF), HALF);
    float qz = __fadd_rn(__fadd_rn(__fmul_rn((float)jz, vs), OFF), HALF);
    float ddx = px - qx, ddy = py - qy, ddz = pz - qz;
    float dd = __fadd_rn(__fadd_rn(__fmul_rn(ddx, ddx), __fmul_rn(ddy, ddy)),
                         __fmul_rn(ddz, ddz));

    ins3(dd, s.x, d0, r0, d1, r1, d2, r2);
    if (s.y != INF_I) {
        ins3(dd, s.y, d0, r0, d1, r1, d2, r2);
        if (s.z != INF_I) ins3(dd, s.z, d0, r0, d1, r1, d2, r2);
    }
}

// ---------------------------------------------------------------------------
__global__ void __launch_bounds__(TPB, 5)
fused(const float* __restrict__ pts,
      const int* __restrict__ x0, const int* __restrict__ x1,
      const int* __restrict__ x2, const int* __restrict__ x3,
      const float* __restrict__ f0, const float* __restrict__ f1,
      const float* __restrict__ f2, const float* __restrict__ f3,
      float* __restrict__ out)
{
    int gtid = blockIdx.x * TPB + threadIdx.x;
    const float OFF = -0.48f;                        // (-0.5*0.015f)*64, exact

    // ---- phase 0: init occupancy maps ----
    for (int i = gtid; i < MCELLS; i += NTHREADS)
        g_map[i] = make_int4(INF_I, INF_I, INF_I, INF_I);
    grid_bar(0);

    // ---- phase 1: scatter rows (3 lowest rows per cell, sorted) ----
    if (gtid < NROWS) {
        int t = gtid;
        const int* inds; int g, base, row;
        if (t < 16000)      { inds = x0; g = 32; base = MB0; row = t; }
        else if (t < 20000) { inds = x1; g = 16; base = MB1; row = t - 16000; }
        else if (t < 20512) { inds = x2; g = 8;  base = MB2; row = t - 20000; }
        else                { inds = x3; g = 4;  base = MB3; row = t - 20512; }
        int4 v = ((const int4*)inds)[row];           // [batch, ix, iy, iz]
        int* s = (int*)&g_map[base + (v.y * g + v.z) * g + v.w];
        int cur = row;
#pragma unroll
        for (int k = 0; k < 3; k++) {
            int old = atomicMin(&s[k], cur);
            cur = max(old, cur);
            if (cur == INF_I) break;
        }
    }
    grid_bar(1);

    // ---- phase 2: half-warp-per-task search + weights + gather ----
    int warp = gtid >> 5;
    int lane = threadIdx.x & 31;
    int hl   = lane & 15;                            // lane within half
    int half = lane >> 4;                            // 0 or 1
    unsigned hmask = half ? 0xFFFF0000u : 0x0000FFFFu;

#pragma unroll 1
    for (int pair = warp; pair < NPAIRS; pair += NWARPS) {
        int task  = pair * 2 + half;                 // scale-major task id
        int scale = task >> 13, point = task & (NPTS - 1);

        const float* f; float vs; int g, base, C4, coff4;
        switch (scale) {
            case 0:  f = f0; vs = 0.015f * 2.0f;  g = 32; base = MB0; C4 = 8;  coff4 = 0;  break;
            case 1:  f = f1; vs = 0.015f * 4.0f;  g = 16; base = MB1; C4 = 16; coff4 = 8;  break;
            case 2:  f = f2; vs = 0.015f * 8.0f;  g = 8;  base = MB2; C4 = 32; coff4 = 24; break;
            default: f = f3; vs = 0.015f * 16.0f; g = 4;  base = MB3; C4 = 64; coff4 = 56; break;
        }
        const float HALF = 0.5f * vs;

        float px = __ldg(&pts[point * 3 + 0]);
        float py = __ldg(&pts[point * 3 + 1]);
        float pz = __ldg(&pts[point * 3 + 2]);

        int cx = min(g - 1, max(0, (int)floorf((px - OFF) / vs)));
        int cy = min(g - 1, max(0, (int)floorf((py - OFF) / vs)));
        int cz = min(g - 1, max(0, (int)floorf((pz - OFF) / vs)));

        float d0 = CUDART_INF_F, d1 = CUDART_INF_F, d2 = CUDART_INF_F;
        int   r0 = INF_I,        r1 = INF_I,        r2 = INF_I;

        // rr=1 cube: lane hl handles cells hl and hl+16 (27 cells total)
#pragma unroll
        for (int k = 0; k < 2; k++) {
            int i = hl + k * 16;
            if (i < 27) {
                int dz = i % 3 - 1;
                int r3 = i / 3;
                int dy = r3 % 3 - 1;
                int dx = r3 / 3 - 1;
                visit_cell(cx + dx, cy + dy, cz + dz, g, base, vs, OFF, HALF,
                           px, py, pz, d0, r0, d1, r1, d2, r2);
            }
        }

        // butterfly merge within the half (disjoint keys -> plain ins3);
        // afterwards all 16 lanes hold the identical sorted top-3.
#pragma unroll
        for (int off = 1; off <= 8; off <<= 1) {
            float e0 = __shfl_xor_sync(hmask, d0, off);
            float e1 = __shfl_xor_sync(hmask, d1, off);
            float e2 = __shfl_xor_sync(hmask, d2, off);
            int   j0 = __shfl_xor_sync(hmask, r0, off);
            int   j1 = __shfl_xor_sync(hmask, r1, off);
            int   j2 = __shfl_xor_sync(hmask, r2, off);
            ins3(e0, j0, d0, r0, d1, r1, d2, r2);
            ins3(e1, j1, d0, r0, d1, r1, d2, r2);
            ins3(e2, j2, d0, r0, d1, r1, d2, r2);
        }

        // local stop test (state identical across the half -> branch uniform)
        {
            float b  = 1.5f * vs * 0.999999f;
            float b2 = b * b;
            int c = (int)(d0 < b2) + (int)(d1 < b2) + (int)(d2 < b2);
            if (c < 3) {
                // rare fallback: expand rings within the half-warp
                int rr = 2;
                while (true) {
                    int side = 2 * rr + 1;
                    int nc = side * side * side;
                    for (int i = hl; i < nc; i += 16) {
                        int t = i;
                        int dz = t % side; t /= side;
                        int dy = t % side;
                        int dx = t / side;
                        dx -= rr; dy -= rr; dz -= rr;
                        int ch = max(max(abs(dx), abs(dy)), abs(dz));
                        if (ch < rr) continue;       // interior already done
                        visit_cell(cx + dx, cy + dy, cz + dz, g, base, vs,
                                   OFF, HALF, px, py, pz,
                                   d0, r0, d1, r1, d2, r2);
                    }
                    // dedup merge (lists share pre-merged entries)
#pragma unroll
                    for (int off = 1; off <= 8; off <<= 1) {
                        float e0 = __shfl_xor_sync(hmask, d0, off);
                        float e1 = __shfl_xor_sync(hmask, d1, off);
                        float e2 = __shfl_xor_sync(hmask, d2, off);
                        int   j0 = __shfl_xor_sync(hmask, r0, off);
                        int   j1 = __shfl_xor_sync(hmask, r1, off);
                        int   j2 = __shfl_xor_sync(hmask, r2, off);
                        ins3d(e0, j0, d0, r0, d1, r1, d2, r2);
                        ins3d(e1, j1, d0, r0, d1, r1, d2, r2);
                        ins3d(e2, j2, d0, r0, d1, r1, d2, r2);
                    }
                    float bb  = ((float)rr + 0.5f) * vs * 0.999999f;
                    float bb2 = bb * bb;
                    int cc = (int)(d0 < bb2) + (int)(d1 < bb2) + (int)(d2 < bb2);
                    if (cc >= 3) break;
                    if (rr >= g) break;              // full grid -> exact
                    rr++;
                }
            }
        }

        // weights (identical on all 16 lanes)
        float a0 = 1.0f / (d0 + 1e-8f);
        float a1 = 1.0f / (d1 + 1e-8f);
        float a2 = 1.0f / (d2 + 1e-8f);
        float inv = 1.0f / (a0 + a1 + a2);
        float w0 = a0 * inv, w1 = a1 * inv, w2 = a2 * inv;

        // half-warp float4 gather
        const float4* p0 = (const float4*)f + (size_t)r0 * C4;
        const float4* p1 = (const float4*)f + (size_t)r1 * C4;
        const float4* p2 = (const float4*)f + (size_t)r2 * C4;
        float4* o = (float4*)out + (size_t)point * 120 + coff4;
        for (int c = hl; c < C4; c += 16) {
            float4 a = p0[c], b = p1[c], d = p2[c], r;
            r.x = w0 * a.x + w1 * b.x + w2 * d.x;
            r.y = w0 * a.y + w1 * b.y + w2 * d.y;
            r.z = w0 * a.z + w1 * b.z + w2 * d.z;
            r.w = w0 * a.w + w1 * b.w + w2 * d.w;
            o[c] = r;
        }
    }
}

// ---------------------------------------------------------------------------
// Inputs identified by element count (all ten distinct):
//   points 24576 | batch_ids 8192 (all-zero, unused by reference)
//   indices: 64000 / 16000 / 2048 / 256
//   feats:   512000 / 256000 / 65536 / 16384
// ---------------------------------------------------------------------------
extern "C" void kernel_launch(void* const* d_in, const int* in_sizes, int n_in,
                              void* d_out, int out_size)
{
    const float* points = nullptr;
    const int* idx[4] = {nullptr, nullptr, nullptr, nullptr};
    const float* feats[4] = {nullptr, nullptr, nullptr, nullptr};

    for (int i = 0; i < n_in; i++) {
        switch (in_sizes[i]) {
            case 24576:  points   = (const float*)d_in[i]; break;
            case 64000:  idx[0]   = (const int*)d_in[i];   break;
            case 16000:  idx[1]   = (const int*)d_in[i];   break;
            case 2048:   idx[2]   = (const int*)d_in[i];   break;
            case 256:    idx[3]   = (const int*)d_in[i];   break;
            case 512000: feats[0] = (const float*)d_in[i]; break;
            case 256000: feats[1] = (const float*)d_in[i]; break;
            case 65536:  feats[2] = (const float*)d_in[i]; break;
            case 16384:  feats[3] = (const float*)d_in[i]; break;
            default: break; // batch_ids unused
        }
    }

    fused<<<GRID, TPB>>>(points, idx[0], idx[1], idx[2], idx[3],
                         feats[0], feats[1], feats[2], feats[3],
                         (float*)d_out);
}

// round 13
// speedup vs baseline: 1.2195x; 1.2195x over previous
#include <cuda_runtime.h>
#include <math_constants.h>

// ---------------------------------------------------------------------------
// Exact 3-NN interpolation via grid ring-search — fused kernel v6.
// Skeleton = R7 (best, 27.1us): persistent grid, two grid barriers, warp-per-
// task search + REDUX head merge + fused gather. Change vs R7: ILP=2 — each
// warp processes task pair (2i, 2i+1) = SAME point, two scales, with the two
// dependency chains interleaved at instruction level:
//   - branch-free load_cell (predicated OOB -> INF quad) so both tasks' map
//     LDGs issue back-to-back before either result is consumed
//   - one packed stop-REDUX for both tasks (cA + cB*256)
//   - REDUX merges with A/B issue interleaved
//   - gathers back-to-back for MLP
//
// Exactness unchanged from R7/R4 (rel_err 6.083e-8 lineage): candidates form
// a total (d2,row) lexicographic order (rows unique per scale; duplicate
// voxels bitwise-equal d2, per-cell slots sorted by row); strict lex insert +
// REDUX head merge = stable jax.lax.top_k. Stop rule: after Chebyshev radius
// rr, any unexamined center is >= (rr+0.5)*vs away; >=3 candidates strictly
// inside the conservatively-shrunk bound => exact; full-grid fallback
// otherwise. Distance math: explicit __fmul_rn/__fadd_rn in reference order.
// ---------------------------------------------------------------------------

#define NPTS   8192
#define INF_I  0x7fffffff
#define INF_FB 0x7f800000u

#define MB0 0
#define MB1 32768
#define MB2 (32768 + 4096)
#define MB3 (32768 + 4096 + 512)
#define MCELLS (32768 + 4096 + 512 + 64)

#define GRID     592                   // 4 blocks/SM * 148 SMs, all resident
#define TPB      256
#define NTHREADS (GRID * TPB)          // 151552
#define NWARPS   (NTHREADS / 32)       // 4736
#define NTASKS   (NPTS * 4)            // 32768 (point-major: task=point*4+scale)
#define NPAIRS   (NTASKS / 2)          // 16384
#define NROWS    20576                 // 16000 + 4000 + 512 + 64

__device__ int4     g_map[MCELLS];
__device__ unsigned g_cnt[2];
__device__ unsigned g_phase[2];        // monotone senses; never reset

__device__ __forceinline__ void grid_bar(int b)
{
    __syncthreads();
    if (threadIdx.x == 0) {
        volatile unsigned* ph = &g_phase[b];
        unsigned p0 = *ph;
        __threadfence();
        unsigned prev = atomicAdd(&g_cnt[b], 1u);
        if (prev == GRID - 1) {
            g_cnt[b] = 0;
            __threadfence();
            *ph = p0 + 1u;
        } else {
            while (*ph == p0) { }
        }
        __threadfence();
    }
    __syncthreads();
}

__device__ __forceinline__ bool diless(float da, int ia, float db, int ib) {
    return (da < db) || (da == db && ia < ib);
}

__device__ __forceinline__ void ins3(float d, int i,
                                     float& d0, int& i0,
                                     float& d1, int& i1,
                                     float& d2, int& i2) {
    if (diless(d, i, d2, i2)) {
        d2 = d; i2 = i;
        if (diless(d2, i2, d1, i1)) { float td = d1; d1 = d2; d2 = td; int ti = i1; i1 = i2; i2 = ti; }
        if (diless(d1, i1, d0, i0)) { float td = d0; d0 = d1; d1 = td; int ti = i0; i0 = i1; i1 = ti; }
    }
}

// Branch-free cell fetch: OOB -> INF quad, no data-dependent branch before
// the consumer, so back-to-back calls put both LDGs in flight.
__device__ __forceinline__ int4 load_cell(int jx, int jy, int jz, int g, int base)
{
    if ((unsigned)jx < (unsigned)g && (unsigned)jy < (unsigned)g &&
        (unsigned)jz < (unsigned)g)
        return g_map[base + (jx * g + jy) * g + jz];
    return make_int4(INF_I, INF_I, INF_I, INF_I);
}

__device__ __forceinline__ void accum_cell(
    int4 s, int jx, int jy, int jz,
    float vs, float OFF, float HALF,
    float px, float py, float pz,
    float& d0, int& r0, float& d1, int& r1, float& d2, int& r2)
{
    if (s.x == INF_I) return;
    float qx = __fadd_rn(__fadd_rn(__fmul_rn((float)jx, vs), OFF), HALF);
    float qy = __fadd_rn(__fadd_rn(__fmul_rn((float)jy, vs), OFF), HALF);
    float qz = __fadd_rn(__fadd_rn(__fmul_rn((float)jz, vs), OFF), HALF);
    float ddx = px - qx, ddy = py - qy, ddz = pz - qz;
    float dd = __fadd_rn(__fadd_rn(__fmul_rn(ddx, ddx), __fmul_rn(ddy, ddy)),
                         __fmul_rn(ddz, ddz));
    ins3(dd, s.x, d0, r0, d1, r1, d2, r2);
    if (s.y != INF_I) {
        ins3(dd, s.y, d0, r0, d1, r1, d2, r2);
        if (s.z != INF_I) ins3(dd, s.z, d0, r0, d1, r1, d2, r2);
    }
}

// Warp-cooperative ring expansion for tasks that fail the rr=1 bound (rare).
// Continues from existing per-lane lists (keys stay globally unique).
__device__ __forceinline__ void ring_fallback(
    int lane, int g, int base, float vs, float OFF, float HALF,
    float px, float py, float pz, int cx, int cy, int cz,
    float& d0, int& r0, float& d1, int& r1, float& d2, int& r2)
{
    int rr = 2;
    while (true) {
        int side = 2 * rr + 1;
        int nc = side * side * side;
        for (int i = lane; i < nc; i += 32) {
            int t = i;
            int dz = t % side; t /= side;
            int dy = t % side;
            int dx = t / side;
            dx -= rr; dy -= rr; dz -= rr;
            int ch = max(max(abs(dx), abs(dy)), abs(dz));
            if (ch < rr) continue;                   // interior already done
            int4 s = load_cell(cx + dx, cy + dy, cz + dz, g, base);
            accum_cell(s, cx + dx, cy + dy, cz + dz, vs, OFF, HALF,
                       px, py, pz, d0, r0, d1, r1, d2, r2);
        }
        float bb  = ((float)rr + 0.5f) * vs * 0.999999f;
        float bb2 = bb * bb;
        int c = (int)(d0 < bb2) + (int)(d1 < bb2) + (int)(d2 < bb2);
        if (__reduce_add_sync(0xffffffffu, c) >= 3) break;
        if (rr >= g) break;                          // full grid -> exact
        rr++;
    }
}

__device__ __forceinline__ void scale_params(int scale,
    const float* f0, const float* f1, const float* f2, const float* f3,
    const float*& f, float& vs, int& g, int& base, int& C4, int& coff4)
{
    switch (scale) {
        case 0:  f = f0; vs = 0.015f * 2.0f;  g = 32; base = MB0; C4 = 8;  coff4 = 0;  break;
        case 1:  f = f1; vs = 0.015f * 4.0f;  g = 16; base = MB1; C4 = 16; coff4 = 8;  break;
        case 2:  f = f2; vs = 0.015f * 8.0f;  g = 8;  base = MB2; C4 = 32; coff4 = 24; break;
        default: f = f3; vs = 0.015f * 16.0f; g = 4;  base = MB3; C4 = 64; coff4 = 56; break;
    }
}

// ---------------------------------------------------------------------------
__global__ void __launch_bounds__(TPB, 4)
fused(const float* __restrict__ pts,
      const int* __restrict__ x0, const int* __restrict__ x1,
      const int* __restrict__ x2, const int* __restrict__ x3,
      const float* __restrict__ f0, const float* __restrict__ f1,
      const float* __restrict__ f2, const float* __restrict__ f3,
      float* __restrict__ out)
{
    int gtid = blockIdx.x * TPB + threadIdx.x;
    const float OFF = -0.48f;                        // (-0.5*0.015f)*64, exact

    // ---- phase 0: init occupancy maps ----
    for (int i = gtid; i < MCELLS; i += NTHREADS)
        g_map[i] = make_int4(INF_I, INF_I, INF_I, INF_I);
    grid_bar(0);

    // ---- phase 1: scatter rows (3 lowest rows per cell, sorted) ----
    if (gtid < NROWS) {
        int t = gtid;
        const int* inds; int g, base, row;
        if (t < 16000)      { inds = x0; g = 32; base = MB0; row = t; }
        else if (t < 20000) { inds = x1; g = 16; base = MB1; row = t - 16000; }
        else if (t < 20512) { inds = x2; g = 8;  base = MB2; row = t - 20000; }
        else                { inds = x3; g = 4;  base = MB3; row = t - 20512; }
        int4 v = ((const int4*)inds)[row];           // [batch, ix, iy, iz]
        int* s = (int*)&g_map[base + (v.y * g + v.z) * g + v.w];
        int cur = row;
#pragma unroll
        for (int k = 0; k < 3; k++) {
            int old = atomicMin(&s[k], cur);
            cur = max(old, cur);
            if (cur == INF_I) break;
        }
    }
    grid_bar(1);

    // ---- phase 2: ILP=2 task pairs (same point, scales s and s+1) ----
    int warp = gtid >> 5;
    int lane = threadIdx.x & 31;

#pragma unroll 1
    for (int p = warp; p < NPAIRS; p += NWARPS) {
        int taskA = 2 * p;                           // point-major ids
        int point = taskA >> 2;
        int sA = taskA & 3;                          // 0 or 2
        int sB = sA + 1;                             // 1 or 3

        const float *fA, *fB; float vsA, vsB; int gA, gB, baseA, baseB;
        int C4A, C4B, coff4A, coff4B;
        scale_params(sA, f0, f1, f2, f3, fA, vsA, gA, baseA, C4A, coff4A);
        scale_params(sB, f0, f1, f2, f3, fB, vsB, gB, baseB, C4B, coff4B);
        const float HA = 0.5f * vsA, HB = 0.5f * vsB;

        float px = __ldg(&pts[point * 3 + 0]);
        float py = __ldg(&pts[point * 3 + 1]);
        float pz = __ldg(&pts[point * 3 + 2]);

        int cxA = min(gA - 1, max(0, (int)floorf((px - OFF) / vsA)));
        int cyA = min(gA - 1, max(0, (int)floorf((py - OFF) / vsA)));
        int czA = min(gA - 1, max(0, (int)floorf((pz - OFF) / vsA)));
        int cxB = min(gB - 1, max(0, (int)floorf((px - OFF) / vsB)));
        int cyB = min(gB - 1, max(0, (int)floorf((py - OFF) / vsB)));
        int czB = min(gB - 1, max(0, (int)floorf((pz - OFF) / vsB)));

        float dA0 = CUDART_INF_F, dA1 = CUDART_INF_F, dA2 = CUDART_INF_F;
        int   rA0 = INF_I,        rA1 = INF_I,        rA2 = INF_I;
        float dB0 = CUDART_INF_F, dB1 = CUDART_INF_F, dB2 = CUDART_INF_F;
        int   rB0 = INF_I,        rB1 = INF_I,        rB2 = INF_I;

        // rr=1: lane < 27 owns one cube offset, used for BOTH tasks.
        // Both LDGs issue before either result is consumed.
        if (lane < 27) {
            int dz = lane % 3 - 1;
            int r3 = lane / 3;
            int dy = r3 % 3 - 1;
            int dx = r3 / 3 - 1;
            int jxA = cxA + dx, jyA = cyA + dy, jzA = czA + dz;
            int jxB = cxB + dx, jyB = cyB + dy, jzB = czB + dz;
            int4 sAq = load_cell(jxA, jyA, jzA, gA, baseA);
            int4 sBq = load_cell(jxB, jyB, jzB, gB, baseB);
            accum_cell(sAq, jxA, jyA, jzA, vsA, OFF, HA, px, py, pz,
                       dA0, rA0, dA1, rA1, dA2, rA2);
            accum_cell(sBq, jxB, jyB, jzB, vsB, OFF, HB, px, py, pz,
                       dB0, rB0, dB1, rB1, dB2, rB2);
        }

        // fused stop test: one packed REDUX for both tasks
        {
            float bA = 1.5f * vsA * 0.999999f; float bA2 = bA * bA;
            float bB = 1.5f * vsB * 0.999999f; float bB2 = bB * bB;
            int cA = (int)(dA0 < bA2) + (int)(dA1 < bA2) + (int)(dA2 < bA2);
            int cB = (int)(dB0 < bB2) + (int)(dB1 < bB2) + (int)(dB2 < bB2);
            int tot = __reduce_add_sync(0xffffffffu, cA + (cB << 8));
            if ((tot & 0xff) < 3)
                ring_fallback(lane, gA, baseA, vsA, OFF, HA, px, py, pz,
                              cxA, cyA, czA, dA0, rA0, dA1, rA1, dA2, rA2);
            if ((tot >> 8) < 3)
                ring_fallback(lane, gB, baseB, vsB, OFF, HB, px, py, pz,
                              cxB, cyB, czB, dB0, rB0, dB1, rB1, dB2, rB2);
        }

        // REDUX 3-way head merges, A/B issue interleaved.
        unsigned hA0 = __float_as_uint(dA0), hA1 = __float_as_uint(dA1),
                 hA2 = __float_as_uint(dA2);
        unsigned hB0 = __float_as_uint(dB0), hB1 = __float_as_uint(dB1),
                 hB2 = __float_as_uint(dB2);
        float wdA[3], wdB[3]; int wrA[3], wrB[3];
#pragma unroll
        for (int k = 0; k < 3; k++) {
            unsigned mA  = __reduce_min_sync(0xffffffffu, hA0);
            unsigned mB  = __reduce_min_sync(0xffffffffu, hB0);
            unsigned rmA = __reduce_min_sync(0xffffffffu,
                               (hA0 == mA) ? (unsigned)rA0 : (unsigned)INF_I);
            unsigned rmB = __reduce_min_sync(0xffffffffu,
                               (hB0 == mB) ? (unsigned)rB0 : (unsigned)INF_I);
            wdA[k] = __uint_as_float(mA); wrA[k] = (int)rmA;
            wdB[k] = __uint_as_float(mB); wrB[k] = (int)rmB;
            if (hA0 == mA && (unsigned)rA0 == rmA) {   // pop my head (A)
                hA0 = hA1; rA0 = rA1; hA1 = hA2; rA1 = rA2;
                hA2 = INF_FB; rA2 = INF_I;
            }
            if (hB0 == mB && (unsigned)rB0 == rmB) {   // pop my head (B)
                hB0 = hB1; rB0 = rB1; hB1 = hB2; rB1 = rB2;
                hB2 = INF_FB; rB2 = INF_I;
            }
        }

        // weights, A/B interleaved (independent MUFU chains)
        float aA0 = 1.0f / (wdA[0] + 1e-8f);
        float aB0 = 1.0f / (wdB[0] + 1e-8f);
        float aA1 = 1.0f / (wdA[1] + 1e-8f);
        float aB1 = 1.0f / (wdB[1] + 1e-8f);
        float aA2 = 1.0f / (wdA[2] + 1e-8f);
        float aB2 = 1.0f / (wdB[2] + 1e-8f);
        float invA = 1.0f / (aA0 + aA1 + aA2);
        float invB = 1.0f / (aB0 + aB1 + aB2);
        float wA0 = aA0 * invA, wA1 = aA1 * invA, wA2 = aA2 * invA;
        float wB0 = aB0 * invB, wB1 = aB1 * invB, wB2 = aB2 * invB;

        // gathers back-to-back (independent load streams)
        {
            const float4* q0 = (const float4*)fA + (size_t)wrA[0] * C4A;
            const float4* q1 = (const float4*)fA + (size_t)wrA[1] * C4A;
            const float4* q2 = (const float4*)fA + (size_t)wrA[2] * C4A;
            float4* o = (float4*)out + (size_t)point * 120 + coff4A;
            for (int c = lane; c < C4A; c += 32) {
                float4 a = q0[c], b = q1[c], d = q2[c], r;
                r.x = wA0 * a.x + wA1 * b.x + wA2 * d.x;
                r.y = wA0 * a.y + wA1 * b.y + wA2 * d.y;
                r.z = wA0 * a.z + wA1 * b.z + wA2 * d.z;
                r.w = wA0 * a.w + wA1 * b.w + wA2 * d.w;
                o[c] = r;
            }
        }
        {
            const float4* q0 = (const float4*)fB + (size_t)wrB[0] * C4B;
            const float4* q1 = (const float4*)fB + (size_t)wrB[1] * C4B;
            const float4* q2 = (const float4*)fB + (size_t)wrB[2] * C4B;
            float4* o = (float4*)out + (size_t)point * 120 + coff4B;
            for (int c = lane; c < C4B; c += 32) {
                float4 a = q0[c], b = q1[c], d = q2[c], r;
                r.x = wB0 * a.x + wB1 * b.x + wB2 * d.x;
                r.y = wB0 * a.y + wB1 * b.y + wB2 * d.y;
                r.z = wB0 * a.z + wB1 * b.z + wB2 * d.z;
                r.w = wB0 * a.w + wB1 * b.w + wB2 * d.w;
                o[c] = r;
            }
        }
    }
}

// ---------------------------------------------------------------------------
// Inputs identified by element count (all ten distinct):
//   points 24576 | batch_ids 8192 (all-zero, unused by reference)
//   indices: 64000 / 16000 / 2048 / 256
//   feats:   512000 / 256000 / 65536 / 16384
// ---------------------------------------------------------------------------
extern "C" void kernel_launch(void* const* d_in, const int* in_sizes, int n_in,
                              void* d_out, int out_size)
{
    const float* points = nullptr;
    const int* idx[4] = {nullptr, nullptr, nullptr, nullptr};
    const float* feats[4] = {nullptr, nullptr, nullptr, nullptr};

    for (int i = 0; i < n_in; i++) {
        switch (in_sizes[i]) {
            case 24576:  points   = (const float*)d_in[i]; break;
            case 64000:  idx[0]   = (const int*)d_in[i];   break;
            case 16000:  idx[1]   = (const int*)d_in[i];   break;
            case 2048:   idx[2]   = (const int*)d_in[i];   break;
            case 256:    idx[3]   = (const int*)d_in[i];   break;
            case 512000: feats[0] = (const float*)d_in[i]; break;
            case 256000: feats[1] = (const float*)d_in[i]; break;
            case 65536:  feats[2] = (const float*)d_in[i]; break;
            case 16384:  feats[3] = (const float*)d_in[i]; break;
            default: break; // batch_ids unused
        }
    }

    fused<<<GRID, TPB>>>(points, idx[0], idx[1], idx[2], idx[3],
                         feats[0], feats[1], feats[2], feats[3],
                         (float*)d_out);
}